// round 14
// baseline (speedup 1.0000x reference)
#include <cuda_runtime.h>
#include <math.h>
#include <stdint.h>

// ---------------------------------------------------------------------------
// SimpleVQ: B=32, H=1, L=4096, D=64, S=512
// out (f32): quantized[NVEC*64] | z[NVEC] | l_commit | errs2[NVEC]
// R13 chassis + Chebyshev-compressed scan: 42 aug dims (32 exact head,
// j>=16 tail via certified deg-8 fit). Gap-certified argmin, rare exact
// fallback, exact dist for outputs.
// ---------------------------------------------------------------------------

typedef unsigned long long ull;

#define NVEC   131072
#define DIMD   64
#define NCODE  512
#define NPAIR  256
#define ZOFF   8388608
#define LOFF   8519680
#define EOFF   8519681
#define NBLK   256
#define JHEAD  16
#define NSEQ   32              // (32-JHEAD)*2 tail sequences
#define NAUG   42              // 32 head + 9 poly + 1 pad
#define NQ     21              // NAUG/2

// ---- smem layout (bytes) ---------------------------------------------------
#define ST4    0               // aug pair-quad table [256][21] float4   86016
#define SCN    86016           // fp32 ||c||^2 [512]                      2048
#define SCF    88064           // coef [32][9] f32                        1152
#define SGE    89216           // E [32] f32                               128
#define SRED   89344           // float[256]                              1024
#define SMEM_BYTES 90368

__device__ float g_cbf[NCODE * 64];    // fp32 codebook rows (refine/fallback/output)
__device__ float g_cn[NCODE];
__device__ float g_rt[NCODE];
__device__ float g_T4[NPAIR * NQ * 4]; // aug pair-quad table
__device__ float g_cf[NSEQ * 9];
__device__ float g_E[NSEQ];
__device__ float g_part[NBLK];

// ---- packed f32x2 helpers (R1/R13-proven) ----------------------------------
__device__ __forceinline__ ull pack2(float x, float y) {
    ull r; asm("mov.b64 %0, {%1, %2};" : "=l"(r) : "f"(x), "f"(y)); return r;
}
__device__ __forceinline__ void unpack2(ull v, float &x, float &y) {
    asm("mov.b64 {%0, %1}, %2;" : "=f"(x), "=f"(y) : "l"(v));
}
__device__ __forceinline__ void ffma2(ull &acc, ull a, ull b) {
    asm("fma.rn.f32x2 %0, %1, %2, %0;" : "+l"(acc) : "l"(a), "l"(b));
}

// ---------------------------------------------------------------------------
// Init 1: codebook (double trig; identical to all passing rounds)
// ---------------------------------------------------------------------------
__global__ void vq_init() {
    __shared__ float red[64];
    const int s = blockIdx.x;
    const int d = threadIdx.x;
    const int j = d & 31;

    double expn = -((double)(2 * j) / 64.0);
    float  il   = (float)pow(100000.0, expn);
    float  pre  = __fmul_rn((float)s, il);
    float  e    = (d < 32) ? (float)sin((double)pre) : (float)cos((double)pre);

    red[d] = __fmul_rn(e, e);
    __syncthreads();
    for (int o = 32; o > 0; o >>= 1) {
        if (d < o) red[d] = __fadd_rn(red[d], red[d + o]);
        __syncthreads();
    }
    float m = __fadd_rn(__fmul_rn(red[0], (1.0f / 64.0f)), 1e-6f);
    __syncthreads();
    float r = (float)(1.0 / sqrt((double)m));
    float c = __fmul_rn(__fmul_rn(e, r), 0.35355339059327373f);

    g_cbf[s * 64 + d] = c;
    if (d == 0) g_rt[s] = __fmul_rn(r, 0.35355339059327373f);

    red[d] = __fmul_rn(c, c);
    __syncthreads();
    for (int o = 32; o > 0; o >>= 1) {
        if (d < o) red[d] = __fadd_rn(red[d], red[d + o]);
        __syncthreads();
    }
    if (d == 0) g_cn[s] = red[0];
}

// ---------------------------------------------------------------------------
// Init 2: deg-8 Chebyshev fits of tail sinusoids (j>=16), certified max-error,
// aug pair-quad table build.
// ---------------------------------------------------------------------------
__global__ void vq_init2() {
    __shared__ float scf[NSEQ][9];
    __shared__ int   seps[NSEQ];
    __shared__ float red[512];
    const int t = threadIdx.x;

    if (t < NSEQ) {
        const int jj = t >> 1, trig = t & 1;
        const int j  = JHEAD + jj;
        float w = (float)pow(100000.0, -((double)(2 * j) / 64.0));
        float c[9];
#pragma unroll
        for (int k = 0; k < 9; k++) c[k] = 0.f;
        for (int mnode = 0; mnode < 33; mnode++) {
            float th = (float)M_PI * ((float)mnode + 0.5f) / 33.f;
            float ct = cosf(th);
            float x  = 255.5f + 255.5f * ct;
            float f  = trig ? cosf(w * x) : sinf(w * x);
            float tk0 = 1.f, tk1 = ct;
            c[0] += f; c[1] += f * ct;
#pragma unroll
            for (int k = 2; k < 9; k++) {
                float tk = 2.f * ct * tk1 - tk0;
                c[k] += f * tk;
                tk0 = tk1; tk1 = tk;
            }
        }
#pragma unroll
        for (int k = 0; k < 9; k++) c[k] *= (2.f / 33.f);
        c[0] *= 0.5f;
#pragma unroll
        for (int k = 0; k < 9; k++) { scf[t][k] = c[k]; g_cf[t * 9 + k] = c[k]; }
        seps[t] = 0;
    }
    __syncthreads();

    const int s = t;
    const float rt = g_rt[s];
    double y = ((double)s - 255.5) / 255.5;
    double T[9];
    T[0] = 1.0; T[1] = y;
#pragma unroll
    for (int k = 2; k < 9; k++) T[k] = 2.0 * y * T[k - 1] - T[k - 2];

    // build aug row A[s][0..41] into pair-quad table
    {
        const int p = s >> 1, col = s & 1;
#pragma unroll
        for (int d = 0; d < NAUG; d++) {
            float val;
            if (d < 16)      val = g_cbf[s * 64 + d];                 // sin head
            else if (d < 32) val = g_cbf[s * 64 + 32 + (d - 16)];     // cos head
            else if (d < 41) val = (float)((double)rt * T[d - 32]);   // poly
            else             val = 0.f;
            g_T4[((p * NQ + (d >> 1)) << 2) + ((d & 1) << 1) + col] = val;
        }
    }

    // certified eps (truth = exact init-1 formula)
    for (int q = 0; q < NSEQ; q++) {
        const int jj = q >> 1, trig = q & 1;
        const int j  = JHEAD + jj;
        double expn = -((double)(2 * j) / 64.0);
        float  il   = (float)pow(100000.0, expn);
        float  pre  = __fmul_rn((float)s, il);
        double truth = trig ? cos((double)pre) : sin((double)pre);
        double fit = 0.0;
#pragma unroll
        for (int k = 0; k < 9; k++) fit += (double)scf[q][k] * T[k];
        float err = (float)fabs(truth - fit);
        atomicMax(&seps[q], __float_as_int(err));
    }

    red[t] = rt;
    __syncthreads();
    for (int o = 256; o > 0; o >>= 1) {
        if (t < o) red[t] = fmaxf(red[t], red[t + o]);
        __syncthreads();
    }
    if (t < NSEQ) g_E[t] = __int_as_float(seps[t]) * red[0];
}

// ---------------------------------------------------------------------------
// exact fp32 distance of one code (ILP-4 dot), R13 dist formula
// ---------------------------------------------------------------------------
__device__ __forceinline__ float exact_dist(const float4* __restrict__ vp,
                                            int code, float vn, const float* scn) {
    const float4* cp = (const float4*)(g_cbf + (size_t)code * 64);
    float d0 = 0.f, d1 = 0.f, d2 = 0.f, d3 = 0.f;
#pragma unroll
    for (int kk = 0; kk < 4; kk++) {
        float4 a0 = vp[4*kk],   b0 = __ldg(cp + 4*kk);
        float4 a1 = vp[4*kk+1], b1 = __ldg(cp + 4*kk+1);
        float4 a2 = vp[4*kk+2], b2 = __ldg(cp + 4*kk+2);
        float4 a3 = vp[4*kk+3], b3 = __ldg(cp + 4*kk+3);
        d0 = fmaf(a0.x, b0.x, d0); d0 = fmaf(a0.y, b0.y, d0);
        d0 = fmaf(a0.z, b0.z, d0); d0 = fmaf(a0.w, b0.w, d0);
        d1 = fmaf(a1.x, b1.x, d1); d1 = fmaf(a1.y, b1.y, d1);
        d1 = fmaf(a1.z, b1.z, d1); d1 = fmaf(a1.w, b1.w, d1);
        d2 = fmaf(a2.x, b2.x, d2); d2 = fmaf(a2.y, b2.y, d2);
        d2 = fmaf(a2.z, b2.z, d2); d2 = fmaf(a2.w, b2.w, d2);
        d3 = fmaf(a3.x, b3.x, d3); d3 = fmaf(a3.y, b3.y, d3);
        d3 = fmaf(a3.z, b3.z, d3); d3 = fmaf(a3.w, b3.w, d3);
    }
    float dot = __fadd_rn(__fadd_rn(d0, d1), __fadd_rn(d2, d3));
    return __fadd_rn(fmaf(-2.f, dot, vn), scn[code]);
}

// ---------------------------------------------------------------------------
__global__ void __launch_bounds__(256) vq_main(const float* __restrict__ vecs,
                                               const float* __restrict__ mask,
                                               float* __restrict__ out) {
    extern __shared__ unsigned char smem[];
    ulonglong2* scb  = (ulonglong2*)(smem + ST4);
    float*      scn  = (float*)(smem + SCN);
    float*      scf  = (float*)(smem + SCF);
    float*      sge  = (float*)(smem + SGE);
    float*      sred = (float*)(smem + SRED);

    const int t = threadIdx.x;
    {
        uint4* d4 = (uint4*)scb;
        const uint4* s4 = (const uint4*)g_T4;
        for (int i = t; i < NPAIR * NQ; i += 256) d4[i] = s4[i];
        for (int i = t; i < NCODE; i += 256) scn[i] = g_cn[i];
        for (int i = t; i < NSEQ * 9; i += 256) scf[i] = g_cf[i];
        if (t < NSEQ) sge[t] = g_E[t];
    }
    __syncthreads();

    const int v0 = blockIdx.x * 512 + t;
    const int v1 = v0 + 256;
    const float4* pa = (const float4*)(vecs + (size_t)v0 * DIMD);
    const float4* pb = (const float4*)(vecs + (size_t)v1 * DIMD);

    // ---- build augmented vectors: vn (exact ascending), head, beta, errb ----
    float ua[NAUG], ub[NAUG];
    float ba[9], bb[9];
#pragma unroll
    for (int k = 0; k < 9; k++) { ba[k] = 0.f; bb[k] = 0.f; }
    float erra = 0.f, errbv = 0.f;
    float vn0 = 0.f, vn1 = 0.f;
    ua[41] = 0.f; ub[41] = 0.f;
#pragma unroll
    for (int i = 0; i < 16; i++) {
        float4 x = pa[i];
        float4 y = pb[i];
        float xa[4] = {x.x, x.y, x.z, x.w};
        float ya[4] = {y.x, y.y, y.z, y.w};
#pragma unroll
        for (int cc = 0; cc < 4; cc++) {
            const int d = 4 * i + cc;
            vn0 = __fadd_rn(vn0, __fmul_rn(xa[cc], xa[cc]));
            vn1 = __fadd_rn(vn1, __fmul_rn(ya[cc], ya[cc]));
            if (d < 16) { ua[d] = xa[cc]; ub[d] = ya[cc]; }
            else if (d < 32) {
                const int q = 2 * (d - 16);
                const float* cf = scf + q * 9;
#pragma unroll
                for (int k = 0; k < 9; k++) {
                    ba[k] = fmaf(xa[cc], cf[k], ba[k]);
                    bb[k] = fmaf(ya[cc], cf[k], bb[k]);
                }
                erra  = fmaf(fabsf(xa[cc]), sge[q], erra);
                errbv = fmaf(fabsf(ya[cc]), sge[q], errbv);
            }
            else if (d < 48) { ua[16 + (d - 32)] = xa[cc]; ub[16 + (d - 32)] = ya[cc]; }
            else {
                const int q = 2 * (d - 48) + 1;
                const float* cf = scf + q * 9;
#pragma unroll
                for (int k = 0; k < 9; k++) {
                    ba[k] = fmaf(xa[cc], cf[k], ba[k]);
                    bb[k] = fmaf(ya[cc], cf[k], bb[k]);
                }
                erra  = fmaf(fabsf(xa[cc]), sge[q], erra);
                errbv = fmaf(fabsf(ya[cc]), sge[q], errbv);
            }
        }
    }
#pragma unroll
    for (int k = 0; k < 9; k++) { ua[32 + k] = ba[k]; ub[32 + k] = bb[k]; }
    const float margA = fmaf(2.f, erra,  0.004f);
    const float margB = fmaf(2.f, errbv, 0.004f);

    // ---- approx scan (R13 inner-loop pattern, 21 quads) ----
    float b1a = 3.4e38f, b2a = 3.4e38f, b1b = 3.4e38f, b2b = 3.4e38f;
    int   bia = 0, bib = 0;

#pragma unroll 1
    for (int p = 0; p < NPAIR; p += 2) {
        ull a00 = 0ull, a01 = 0ull, a10 = 0ull, a11 = 0ull;
#pragma unroll
        for (int j = 0; j < NQ; j++) {
            ulonglong2 c0 = scb[(p + 0) * NQ + j];
            ulonglong2 c1 = scb[(p + 1) * NQ + j];
            ull w0 = pack2(ua[2*j],     ua[2*j]);
            ull w1 = pack2(ua[2*j + 1], ua[2*j + 1]);
            ull u0 = pack2(ub[2*j],     ub[2*j]);
            ull u1 = pack2(ub[2*j + 1], ub[2*j + 1]);
            ffma2(a00, w0, c0.x); ffma2(a00, w1, c0.y);
            ffma2(a01, w0, c1.x); ffma2(a01, w1, c1.y);
            ffma2(a10, u0, c0.x); ffma2(a10, u1, c0.y);
            ffma2(a11, u0, c1.x); ffma2(a11, u1, c1.y);
        }
        float q0, q1, q2, q3, r0, r1, r2, r3;
        unpack2(a00, q0, q1); unpack2(a01, q2, q3);
        unpack2(a10, r0, r1); unpack2(a11, r2, r3);
        const int s0 = 2 * p;
        const float cna = scn[s0], cnb = scn[s0 + 1], cnc = scn[s0 + 2], cnd = scn[s0 + 3];
        float d0 = __fadd_rn(fmaf(-2.f, q0, vn0), cna);
        float d1 = __fadd_rn(fmaf(-2.f, q1, vn0), cnb);
        float d2 = __fadd_rn(fmaf(-2.f, q2, vn0), cnc);
        float d3 = __fadd_rn(fmaf(-2.f, q3, vn0), cnd);
        if (d0 < b1a) { b2a = b1a; b1a = d0; bia = s0;     } else if (d0 < b2a) b2a = d0;
        if (d1 < b1a) { b2a = b1a; b1a = d1; bia = s0 + 1; } else if (d1 < b2a) b2a = d1;
        if (d2 < b1a) { b2a = b1a; b1a = d2; bia = s0 + 2; } else if (d2 < b2a) b2a = d2;
        if (d3 < b1a) { b2a = b1a; b1a = d3; bia = s0 + 3; } else if (d3 < b2a) b2a = d3;
        float e0 = __fadd_rn(fmaf(-2.f, r0, vn1), cna);
        float e1 = __fadd_rn(fmaf(-2.f, r1, vn1), cnb);
        float e2 = __fadd_rn(fmaf(-2.f, r2, vn1), cnc);
        float e3 = __fadd_rn(fmaf(-2.f, r3, vn1), cnd);
        if (e0 < b1b) { b2b = b1b; b1b = e0; bib = s0;     } else if (e0 < b2b) b2b = e0;
        if (e1 < b1b) { b2b = b1b; b1b = e1; bib = s0 + 1; } else if (e1 < b2b) b2b = e1;
        if (e2 < b1b) { b2b = b1b; b1b = e2; bib = s0 + 2; } else if (e2 < b2b) b2b = e2;
        if (e3 < b1b) { b2b = b1b; b1b = e3; bib = s0 + 3; } else if (e3 < b2b) b2b = e3;
    }

    // ---- certify or fallback ----
    float bestd0, bestd1;
    if (b2a - b1a >= margA) {
        bestd0 = exact_dist(pa, bia, vn0, scn);
    } else {
        bestd0 = 3.4e38f; bia = 0;
        for (int code = 0; code < NCODE; code++) {
            float dd = exact_dist(pa, code, vn0, scn);
            if (dd < bestd0) { bestd0 = dd; bia = code; }
        }
    }
    if (b2b - b1b >= margB) {
        bestd1 = exact_dist(pb, bib, vn1, scn);
    } else {
        bestd1 = 3.4e38f; bib = 0;
        for (int code = 0; code < NCODE; code++) {
            float dd = exact_dist(pb, code, vn1, scn);
            if (dd < bestd1) { bestd1 = dd; bib = code; }
        }
    }

    // ---- outputs ----
    {
        const float4* cp = (const float4*)(g_cbf + (size_t)bia * 64);
        float4* dst = (float4*)(out + (size_t)v0 * DIMD);
#pragma unroll
        for (int i = 0; i < 16; i++) dst[i] = __ldg(cp + i);
    }
    {
        const float4* cp = (const float4*)(g_cbf + (size_t)bib * 64);
        float4* dst = (float4*)(out + (size_t)v1 * DIMD);
#pragma unroll
        for (int i = 0; i < 16; i++) dst[i] = __ldg(cp + i);
    }
    out[ZOFF + v0] = (float)bia;
    out[ZOFF + v1] = (float)bib;
    float er0 = fmaxf(bestd0, 0.f);
    float er1 = fmaxf(bestd1, 0.f);
    out[EOFF + v0] = er0;
    out[EOFF + v1] = er1;

    float lsum = __fadd_rn(__fmul_rn(mask[v0], er0), __fmul_rn(mask[v1], er1));
    sred[t] = lsum;
    __syncthreads();
    for (int o = 128; o > 0; o >>= 1) {
        if (t < o) sred[t] = __fadd_rn(sred[t], sred[t + o]);
        __syncthreads();
    }
    if (t == 0) g_part[blockIdx.x] = sred[0];
}

// ---------------------------------------------------------------------------
__global__ void vq_final(float* __restrict__ out) {
    __shared__ float s[NBLK];
    int t = threadIdx.x;
    s[t] = g_part[t];
    __syncthreads();
    for (int o = NBLK / 2; o > 0; o >>= 1) {
        if (t < o) s[t] = __fadd_rn(s[t], s[t + o]);
        __syncthreads();
    }
    if (t == 0) out[LOFF] = __fmul_rn(s[0], (1.0f / 131072.0f));
}

// ---------------------------------------------------------------------------
extern "C" void kernel_launch(void* const* d_in, const int* in_sizes, int n_in,
                              void* d_out, int out_size) {
    (void)in_sizes; (void)n_in; (void)out_size;
    const float* vecs = (const float*)d_in[0];
    const float* mask = (const float*)d_in[1];
    float* out = (float*)d_out;

    cudaFuncSetAttribute(vq_main, cudaFuncAttributeMaxDynamicSharedMemorySize, SMEM_BYTES);

    vq_init<<<NCODE, 64>>>();
    vq_init2<<<1, 512>>>();
    vq_main<<<NBLK, 256, SMEM_BYTES>>>(vecs, mask, out);
    vq_final<<<1, NBLK>>>(out);
}

// round 15
// speedup vs baseline: 2.1858x; 2.1858x over previous
#include <cuda_runtime.h>
#include <math.h>
#include <stdint.h>

// ---------------------------------------------------------------------------
// SimpleVQ: B=32, H=1, L=4096, D=64, S=512
// out (f32): quantized[NVEC*64] | z[NVEC] | l_commit | errs2[NVEC]
// R13 exact FFMA2 scan, persistent 148 blocks, 128-vec tiles with
// 2-threads-per-vector half-codebook split -> wave quantization 1.012.
// ---------------------------------------------------------------------------

typedef unsigned long long ull;

#define NVEC   131072
#define DIMD   64
#define NCODE  512
#define NPAIR  256
#define ZOFF   8388608
#define LOFF   8519680
#define EOFF   8519681
#define NBLK   148
#define NTHR   256
#define NTILES 1024            // NVEC / 128

// ---- smem layout (bytes) ---------------------------------------------------
#define SCB    0               // pair-quad codebook [256][32] float4  131072
#define SCN    131072          // fp32 ||c||^2 [512]                     2048
#define SKEY   133120          // ull [128]                              1024
#define SRED   134144          // float [256]                            1024
#define SMEM_BYTES 135168

// pair-quad layout (R1): g_cbq[p*32+j] = { c[2p][2j], c[2p+1][2j], c[2p][2j+1], c[2p+1][2j+1] }
__device__ float4 g_cbq[NPAIR * 32];
__device__ float  g_cn[NCODE];
__device__ float  g_part[NBLK];

// ---- packed f32x2 helpers (R1/R13-proven) ----------------------------------
__device__ __forceinline__ ull pack2(float x, float y) {
    ull r; asm("mov.b64 %0, {%1, %2};" : "=l"(r) : "f"(x), "f"(y)); return r;
}
__device__ __forceinline__ void unpack2(ull v, float &x, float &y) {
    asm("mov.b64 {%0, %1}, %2;" : "=f"(x), "=f"(y) : "l"(v));
}
__device__ __forceinline__ void ffma2(ull &acc, ull a, ull b) {
    asm("fma.rn.f32x2 %0, %1, %2, %0;" : "+l"(acc) : "l"(a), "l"(b));
}
__device__ __forceinline__ uint32_t enc32(float f) {
    uint32_t u = __float_as_uint(f);
    return (u & 0x80000000u) ? ~u : (u | 0x80000000u);
}
__device__ __forceinline__ float dec32(uint32_t m) {
    uint32_t u = (m & 0x80000000u) ? (m & 0x7FFFFFFFu) : ~m;
    return __uint_as_float(u);
}

// ---------------------------------------------------------------------------
// Init: 512 blocks x 64 threads (R13-proven, ~5.4us)
// ---------------------------------------------------------------------------
__global__ void vq_init() {
    __shared__ float red[64];
    const int s = blockIdx.x;
    const int d = threadIdx.x;
    const int j = d & 31;

    double expn = -((double)(2 * j) / 64.0);
    float  il   = (float)pow(100000.0, expn);
    float  pre  = __fmul_rn((float)s, il);
    float  e    = (d < 32) ? (float)sin((double)pre) : (float)cos((double)pre);

    red[d] = __fmul_rn(e, e);
    __syncthreads();
    for (int o = 32; o > 0; o >>= 1) {
        if (d < o) red[d] = __fadd_rn(red[d], red[d + o]);
        __syncthreads();
    }
    float m = __fadd_rn(__fmul_rn(red[0], (1.0f / 64.0f)), 1e-6f);
    __syncthreads();
    float r = (float)(1.0 / sqrt((double)m));
    float c = __fmul_rn(__fmul_rn(e, r), 0.35355339059327373f);

    float* cb = (float*)g_cbq;
    const int p = s >> 1, col = s & 1;
    cb[(p * 32 + (d >> 1)) * 4 + (d & 1) * 2 + col] = c;

    red[d] = __fmul_rn(c, c);
    __syncthreads();
    for (int o = 32; o > 0; o >>= 1) {
        if (d < o) red[d] = __fadd_rn(red[d], red[d + o]);
        __syncthreads();
    }
    if (d == 0) g_cn[s] = red[0];
}

// ---------------------------------------------------------------------------
// Main: persistent 148 blocks x 256 threads. Tile = 128 vectors; each vector
// handled by 2 threads (code halves 0-255 / 256-511); merge via skey atomicMin.
// Inner loop: R1's broadcast-LDS + FFMA2 pattern, 4 accumulators.
// ---------------------------------------------------------------------------
__global__ void __launch_bounds__(NTHR) vq_main(const float* __restrict__ vecs,
                                                const float* __restrict__ mask,
                                                float* __restrict__ out) {
    extern __shared__ unsigned char smem[];
    float4*     scbf = (float4*)(smem + SCB);
    ulonglong2* scb  = (ulonglong2*)(smem + SCB);
    float*      scn  = (float*)(smem + SCN);
    ull*        skey = (ull*)(smem + SKEY);
    float*      sred = (float*)(smem + SRED);

    const int t = threadIdx.x;
    const int h = t >> 7;            // code half: 0 or 1 (warp-uniform)
    const int r = t & 127;           // row within tile

    for (int i = t; i < NPAIR * 32; i += NTHR) scbf[i] = g_cbq[i];
    for (int i = t; i < NCODE; i += NTHR) scn[i] = g_cn[i];
    __syncthreads();

    float lacc = 0.f;

    for (int tile = blockIdx.x; tile < NTILES; tile += NBLK) {
        const int vglob = tile * 128 + r;
        const float4* pa = (const float4*)(vecs + (size_t)vglob * DIMD);

        // ---- load vector + exact ascending vn (R1 semantics) ----
        float va[64];
#pragma unroll
        for (int i = 0; i < 16; i++) {
            float4 x = pa[i];
            va[4*i] = x.x; va[4*i+1] = x.y; va[4*i+2] = x.z; va[4*i+3] = x.w;
        }
        float vn = 0.f;
#pragma unroll
        for (int d = 0; d < 64; d++) vn = __fadd_rn(vn, __fmul_rn(va[d], va[d]));

        if (t < 128) skey[t] = ~0ull;
        __syncthreads();

        // ---- scan this thread's half: 128 pairs, 4 pairs per outer iter ----
        float best = 3.4e38f;
        int   bi   = h * 256;
        const int pbase = h * 128;

#pragma unroll 1
        for (int pp = 0; pp < 128; pp += 4) {
            const int p0 = pbase + pp;
            ull a0 = 0ull, a1 = 0ull, a2 = 0ull, a3 = 0ull;
#pragma unroll
            for (int j = 0; j < 32; j++) {
                ulonglong2 c0 = scb[(p0 + 0) * 32 + j];
                ulonglong2 c1 = scb[(p0 + 1) * 32 + j];
                ulonglong2 c2 = scb[(p0 + 2) * 32 + j];
                ulonglong2 c3 = scb[(p0 + 3) * 32 + j];
                ull w0 = pack2(va[2*j],     va[2*j]);
                ull w1 = pack2(va[2*j + 1], va[2*j + 1]);
                ffma2(a0, w0, c0.x); ffma2(a0, w1, c0.y);
                ffma2(a1, w0, c1.x); ffma2(a1, w1, c1.y);
                ffma2(a2, w0, c2.x); ffma2(a2, w1, c2.y);
                ffma2(a3, w0, c3.x); ffma2(a3, w1, c3.y);
            }
            float q0, q1, q2, q3, q4, q5, q6, q7;
            unpack2(a0, q0, q1); unpack2(a1, q2, q3);
            unpack2(a2, q4, q5); unpack2(a3, q6, q7);
            const int s0 = 2 * p0;
            float d0 = __fadd_rn(fmaf(-2.f, q0, vn), scn[s0]);
            float d1 = __fadd_rn(fmaf(-2.f, q1, vn), scn[s0 + 1]);
            float d2 = __fadd_rn(fmaf(-2.f, q2, vn), scn[s0 + 2]);
            float d3 = __fadd_rn(fmaf(-2.f, q3, vn), scn[s0 + 3]);
            float d4 = __fadd_rn(fmaf(-2.f, q4, vn), scn[s0 + 4]);
            float d5 = __fadd_rn(fmaf(-2.f, q5, vn), scn[s0 + 5]);
            float d6 = __fadd_rn(fmaf(-2.f, q6, vn), scn[s0 + 6]);
            float d7 = __fadd_rn(fmaf(-2.f, q7, vn), scn[s0 + 7]);
            if (d0 < best) { best = d0; bi = s0;     }
            if (d1 < best) { best = d1; bi = s0 + 1; }
            if (d2 < best) { best = d2; bi = s0 + 2; }
            if (d3 < best) { best = d3; bi = s0 + 3; }
            if (d4 < best) { best = d4; bi = s0 + 4; }
            if (d5 < best) { best = d5; bi = s0 + 5; }
            if (d6 < best) { best = d6; bi = s0 + 6; }
            if (d7 < best) { best = d7; bi = s0 + 7; }
        }

        // ---- merge halves: (dist, code) key, min = first-min-wins ----
        atomicMin(&skey[r], ((ull)enc32(best) << 9) | (uint32_t)bi);
        __syncthreads();

        const ull key = skey[r];
        const int bs  = (int)(key & 511);

        // ---- outputs: this thread writes its 32-dim half of quantized ----
        {
            const int pw = bs >> 1, col = bs & 1;
            float2* dst = (float2*)(out + (size_t)vglob * DIMD + h * 32);
#pragma unroll
            for (int j = 0; j < 16; j++) {
                float4 q = scbf[pw * 32 + (h * 16 + j)];
                float2 w; w.x = col ? q.y : q.x; w.y = col ? q.w : q.z;
                dst[j] = w;
            }
        }
        if (h == 0) {
            float dist = dec32((uint32_t)(key >> 9));
            float er = fmaxf(dist, 0.f);
            out[ZOFF + vglob] = (float)bs;
            out[EOFF + vglob] = er;
            lacc = __fadd_rn(lacc, __fmul_rn(mask[vglob], er));
        }
        __syncthreads();
    }

    // ---- l_commit block partial (deterministic static assignment) ----
    sred[t] = lacc;
    __syncthreads();
    for (int o = NTHR / 2; o > 0; o >>= 1) {
        if (t < o) sred[t] = __fadd_rn(sred[t], sred[t + o]);
        __syncthreads();
    }
    if (t == 0) g_part[blockIdx.x] = sred[0];
}

// ---------------------------------------------------------------------------
__global__ void vq_final(float* __restrict__ out) {
    __shared__ float s[256];
    int t = threadIdx.x;
    s[t] = (t < NBLK) ? g_part[t] : 0.f;
    __syncthreads();
    for (int o = 128; o > 0; o >>= 1) {
        if (t < o) s[t] = __fadd_rn(s[t], s[t + o]);
        __syncthreads();
    }
    if (t == 0) out[LOFF] = __fmul_rn(s[0], (1.0f / 131072.0f));
}

// ---------------------------------------------------------------------------
extern "C" void kernel_launch(void* const* d_in, const int* in_sizes, int n_in,
                              void* d_out, int out_size) {
    (void)in_sizes; (void)n_in; (void)out_size;
    const float* vecs = (const float*)d_in[0];
    const float* mask = (const float*)d_in[1];
    float* out = (float*)d_out;

    cudaFuncSetAttribute(vq_main, cudaFuncAttributeMaxDynamicSharedMemorySize, SMEM_BYTES);

    vq_init<<<NCODE, 64>>>();
    vq_main<<<NBLK, NTHR, SMEM_BYTES>>>(vecs, mask, out);
    vq_final<<<1, 256>>>(out);
}

// round 16
// speedup vs baseline: 2.6878x; 1.2297x over previous
#include <cuda_runtime.h>
#include <math.h>

// ---------------------------------------------------------------------------
// SimpleVQ: B=32, H=1, L=4096, D=64, S=512
// Outputs (f32): quantized[B*H*L*D] | z[B*H*L] | l_commit | errs2[B*H*L]
// R13 (roofline-verified exact FFMA2 scan, 243.8us) + fused final reduction.
// ---------------------------------------------------------------------------

typedef unsigned long long ull;

#define NVEC   131072
#define DIMD   64
#define NCODE  512
#define NPAIR  256
#define ZOFF   8388608
#define LOFF   8519680
#define EOFF   8519681
#define NBLK   256
#define SMEM_BYTES (131072 + 2048 + 1024)

__device__ float4 g_cbq[NPAIR * 32];
__device__ float  g_cn[NCODE];
__device__ float  g_part[NBLK];
__device__ int    g_ticket;

// ---- packed f32x2 helpers --------------------------------------------------
__device__ __forceinline__ ull pack2(float x, float y) {
    ull r; asm("mov.b64 %0, {%1, %2};" : "=l"(r) : "f"(x), "f"(y)); return r;
}
__device__ __forceinline__ void unpack2(ull v, float &x, float &y) {
    asm("mov.b64 {%0, %1}, %2;" : "=f"(x), "=f"(y) : "l"(v));
}
__device__ __forceinline__ void ffma2(ull &acc, ull a, ull b) {
    asm("fma.rn.f32x2 %0, %1, %2, %0;" : "+l"(acc) : "l"(a), "l"(b));
}

// ---------------------------------------------------------------------------
// Init: 512 blocks x 64 threads; double trig; writes pair-quad layout.
// Also resets the ticket (deterministic across graph replays).
// ---------------------------------------------------------------------------
__global__ void vq_init() {
    __shared__ float red[64];
    const int s = blockIdx.x;
    const int d = threadIdx.x;
    const int j = d & 31;
    if (s == 0 && d == 0) g_ticket = 0;

    double expn = -((double)(2 * j) / 64.0);
    float  il   = (float)pow(100000.0, expn);
    float  pre  = __fmul_rn((float)s, il);
    float  e    = (d < 32) ? (float)sin((double)pre) : (float)cos((double)pre);

    red[d] = __fmul_rn(e, e);
    __syncthreads();
    for (int o = 32; o > 0; o >>= 1) {
        if (d < o) red[d] = __fadd_rn(red[d], red[d + o]);
        __syncthreads();
    }
    float m = __fadd_rn(__fmul_rn(red[0], (1.0f / 64.0f)), 1e-6f);
    __syncthreads();
    float r = (float)(1.0 / sqrt((double)m));
    float c = __fmul_rn(__fmul_rn(e, r), 0.35355339059327373f);

    float* cb = (float*)g_cbq;
    const int p = s >> 1, col = s & 1;
    cb[(p * 32 + (d >> 1)) * 4 + (d & 1) * 2 + col] = c;

    red[d] = __fmul_rn(c, c);
    __syncthreads();
    for (int o = 32; o > 0; o >>= 1) {
        if (d < o) red[d] = __fadd_rn(red[d], red[d + o]);
        __syncthreads();
    }
    if (d == 0) g_cn[s] = red[0];
}

// ---------------------------------------------------------------------------
// Main: verbatim R13 scan (roofline-optimal) + last-block l_commit reduction.
// ---------------------------------------------------------------------------
__global__ void __launch_bounds__(256) vq_main(const float* __restrict__ vecs,
                                               const float* __restrict__ mask,
                                               float* __restrict__ out) {
    extern __shared__ unsigned char smem[];
    float4*     scbf = (float4*)smem;
    ulonglong2* scb  = (ulonglong2*)smem;
    float*      scn  = (float*)(smem + 131072);
    float*      sred = scn + NCODE;

    for (int i = threadIdx.x; i < NPAIR * 32; i += 256) scbf[i] = g_cbq[i];
    for (int i = threadIdx.x; i < NCODE; i += 256) scn[i] = g_cn[i];
    __syncthreads();

    const int t  = threadIdx.x;
    const int v0 = blockIdx.x * 512 + t;
    const int v1 = v0 + 256;

    float va[64], vb[64];
    {
        const float4* pa = (const float4*)(vecs + (size_t)v0 * DIMD);
        const float4* pb = (const float4*)(vecs + (size_t)v1 * DIMD);
#pragma unroll
        for (int i = 0; i < 16; i++) {
            float4 x = pa[i];
            va[4*i] = x.x; va[4*i+1] = x.y; va[4*i+2] = x.z; va[4*i+3] = x.w;
            float4 y = pb[i];
            vb[4*i] = y.x; vb[4*i+1] = y.y; vb[4*i+2] = y.z; vb[4*i+3] = y.w;
        }
    }
    float vn0 = 0.f, vn1 = 0.f;
#pragma unroll
    for (int d = 0; d < 64; d++) {
        vn0 = __fadd_rn(vn0, __fmul_rn(va[d], va[d]));
        vn1 = __fadd_rn(vn1, __fmul_rn(vb[d], vb[d]));
    }

    float best0 = 3.4e38f, best1 = 3.4e38f;
    int   bi0 = 0, bi1 = 0;

#pragma unroll 1
    for (int p = 0; p < NPAIR; p += 2) {
        ull a00 = 0ull, a01 = 0ull, a10 = 0ull, a11 = 0ull;
#pragma unroll
        for (int j = 0; j < 32; j++) {
            ulonglong2 c0 = scb[(p + 0) * 32 + j];
            ulonglong2 c1 = scb[(p + 1) * 32 + j];
            ull w0 = pack2(va[2*j],     va[2*j]);
            ull w1 = pack2(va[2*j + 1], va[2*j + 1]);
            ull u0 = pack2(vb[2*j],     vb[2*j]);
            ull u1 = pack2(vb[2*j + 1], vb[2*j + 1]);
            ffma2(a00, w0, c0.x); ffma2(a00, w1, c0.y);
            ffma2(a01, w0, c1.x); ffma2(a01, w1, c1.y);
            ffma2(a10, u0, c0.x); ffma2(a10, u1, c0.y);
            ffma2(a11, u0, c1.x); ffma2(a11, u1, c1.y);
        }
        float q0, q1, q2, q3, r0, r1, r2, r3;
        unpack2(a00, q0, q1); unpack2(a01, q2, q3);
        unpack2(a10, r0, r1); unpack2(a11, r2, r3);
        const int s0 = 2 * p;
        const float cna = scn[s0], cnb = scn[s0 + 1], cnc = scn[s0 + 2], cnd = scn[s0 + 3];
        float d0 = __fadd_rn(fmaf(-2.f, q0, vn0), cna);
        float d1 = __fadd_rn(fmaf(-2.f, q1, vn0), cnb);
        float d2 = __fadd_rn(fmaf(-2.f, q2, vn0), cnc);
        float d3 = __fadd_rn(fmaf(-2.f, q3, vn0), cnd);
        if (d0 < best0) { best0 = d0; bi0 = s0;     }
        if (d1 < best0) { best0 = d1; bi0 = s0 + 1; }
        if (d2 < best0) { best0 = d2; bi0 = s0 + 2; }
        if (d3 < best0) { best0 = d3; bi0 = s0 + 3; }
        float e0 = __fadd_rn(fmaf(-2.f, r0, vn1), cna);
        float e1 = __fadd_rn(fmaf(-2.f, r1, vn1), cnb);
        float e2 = __fadd_rn(fmaf(-2.f, r2, vn1), cnc);
        float e3 = __fadd_rn(fmaf(-2.f, r3, vn1), cnd);
        if (e0 < best1) { best1 = e0; bi1 = s0;     }
        if (e1 < best1) { best1 = e1; bi1 = s0 + 1; }
        if (e2 < best1) { best1 = e2; bi1 = s0 + 2; }
        if (e3 < best1) { best1 = e3; bi1 = s0 + 3; }
    }

    {
        int pw = bi0 >> 1, col = bi0 & 1;
        float2* dst = (float2*)(out + (size_t)v0 * DIMD);
#pragma unroll
        for (int j = 0; j < 32; j++) {
            float4 q = scbf[pw * 32 + j];
            float2 w; w.x = col ? q.y : q.x; w.y = col ? q.w : q.z;
            dst[j] = w;
        }
    }
    {
        int pw = bi1 >> 1, col = bi1 & 1;
        float2* dst = (float2*)(out + (size_t)v1 * DIMD);
#pragma unroll
        for (int j = 0; j < 32; j++) {
            float4 q = scbf[pw * 32 + j];
            float2 w; w.x = col ? q.y : q.x; w.y = col ? q.w : q.z;
            dst[j] = w;
        }
    }

    out[ZOFF + v0] = (float)bi0;
    out[ZOFF + v1] = (float)bi1;
    float er0 = fmaxf(best0, 0.f);
    float er1 = fmaxf(best1, 0.f);
    out[EOFF + v0] = er0;
    out[EOFF + v1] = er1;

    float lsum = __fadd_rn(__fmul_rn(mask[v0], er0), __fmul_rn(mask[v1], er1));
    sred[t] = lsum;
    __syncthreads();
    for (int o = 128; o > 0; o >>= 1) {
        if (t < o) sred[t] = __fadd_rn(sred[t], sred[t + o]);
        __syncthreads();
    }

    // ---- fused final: last block reduces g_part deterministically ----
    __shared__ int slast;
    if (t == 0) {
        g_part[blockIdx.x] = sred[0];
        __threadfence();
        int ticket = atomicAdd(&g_ticket, 1);
        slast = (ticket == NBLK - 1) ? 1 : 0;
        if (slast) g_ticket = 0;          // reset for next graph replay
    }
    __syncthreads();
    if (slast) {
        sred[t] = g_part[t];              // 256 partials, fixed order
        __syncthreads();
        for (int o = 128; o > 0; o >>= 1) {
            if (t < o) sred[t] = __fadd_rn(sred[t], sred[t + o]);
            __syncthreads();
        }
        if (t == 0) out[LOFF] = __fmul_rn(sred[0], (1.0f / 131072.0f));
    }
}

// ---------------------------------------------------------------------------
extern "C" void kernel_launch(void* const* d_in, const int* in_sizes, int n_in,
                              void* d_out, int out_size) {
    (void)in_sizes; (void)n_in; (void)out_size;
    const float* vecs = (const float*)d_in[0];
    const float* mask = (const float*)d_in[1];
    float* out = (float*)d_out;

    cudaFuncSetAttribute(vq_main, cudaFuncAttributeMaxDynamicSharedMemorySize, SMEM_BYTES);

    vq_init<<<NCODE, 64>>>();
    vq_main<<<NBLK, 256, SMEM_BYTES>>>(vecs, mask, out);
}